// round 9
// baseline (speedup 1.0000x reference)
#include <cuda_runtime.h>

#define NC 19
#define BB 8
#define HH 512
#define WIDTH 512
#define HW (HH*WIDTH)
#define WW 16
#define HALO 20
#define STRIP 128
#define RB (STRIP + 2*HALO)   // 168 window rows
#define NSTRIP (HH/STRIP)     // 4
#define NBLK (BB*NC*NSTRIP)   // 608
#define IWORDS (STRIP*WW)     // 2048 interior words
#define TPB 192
#define TSTRIDE 17
#define TPLANE (STRIP*TSTRIDE) // 2176
#define NB3 2048              // k_loss blocks (4 px/thread)

// Scratch (static device globals; allocation-free)
__device__ unsigned       g_bits[(size_t)BB*NC*HH*WW];  // ~5 MB packed class masks
__device__ unsigned char  g_dist[(size_t)BB*NC*HW];     // 40 MB distances (0..20)
__device__ unsigned       g_t4[(size_t)NBLK*IWORDS];    // 5 MB: rare 5th first-set plane
__device__ float          g_part[NB3];

// Fast exp on the FMA pipe (|rel err| ~3e-6)
__device__ __forceinline__ float fexp(float x) {
    float y = x * 1.4426950408889634f;
    y = fmaxf(y, -80.0f);
    float z = y + 12582912.0f;
    int   n = __float_as_int(z) - 0x4B400000;
    float f = y - (z - 12582912.0f);
    float p =          1.3333558e-3f;
    p = fmaf(p, f, 9.6181291e-3f);
    p = fmaf(p, f, 5.5504109e-2f);
    p = fmaf(p, f, 2.4022651e-1f);
    p = fmaf(p, f, 6.9314718e-1f);
    p = fmaf(p, f, 1.0f);
    return __int_as_float(__float_as_int(p) + (n << 23));
}

// K0: bit-pack per-class masks via warp ballots (target int32)
__global__ void k_bits(const int* __restrict__ tgt) {
    int g    = blockIdx.x * blockDim.x + threadIdx.x;
    int lane = g & 31;
    int wid  = g >> 5;
    int ww   = wid & 15;
    int h    = (wid >> 4) & 511;
    int b    = wid >> 13;
    int lab  = tgt[(size_t)(b * HH + h) * WIDTH + ww * 32 + lane];
    unsigned my = 0;
#pragma unroll
    for (int c = 0; c < NC; ++c) {
        unsigned bal = __ballot_sync(0xffffffffu, lab == c);
        if (lane == c) my = bal;
    }
    if (lane < NC)
        g_bits[((size_t)(b * NC + lane) * HH + h) * WW + ww] = my;
}

// K1: row-per-thread bitwise dilation. Thread r holds window row r in regs;
// per iter: store H=row|G rows to smem, read up/dn H rows back. First-set
// planes (17-padded) give dist = first_set - m0bit; zero-clamped padding;
// interior saturation exit; all-ones rows self-skip.
__global__ void __launch_bounds__(TPB, 4) k_dilate() {
    __shared__ unsigned Hb[RB * TSTRIDE];   // H rows / staging (2856 words)
    __shared__ unsigned T[4 * TPLANE];      // first-set bit planes 0..3

    int blk = blockIdx.x;
    int s   = blk & 3;
    int t2  = blk >> 2;
    int c   = t2 % NC;
    int b   = t2 / NC;
    int tid = threadIdx.x;
    int r   = tid;
    bool act = (r < RB);
    int g0  = s * STRIP - HALO;

    const unsigned* mbase = g_bits + (size_t)(b * NC + c) * HH * WW;
    unsigned* t4 = g_t4 + (size_t)blk * IWORDS;

    // coalesced load of the window into staging (out-of-image rows -> 0)
    for (int i = tid; i < RB * WW; i += TPB) {
        int rr = i >> 4, g = g0 + rr;
        Hb[rr * TSTRIDE + (i & 15)] = (g >= 0 && g < HH) ? mbase[(size_t)g * WW + (i & 15)] : 0u;
    }
    for (int i = tid; i < 4 * TPLANE; i += TPB) T[i] = 0u;
    for (int i = tid; i < IWORDS; i += TPB) t4[i] = 0u;
    __syncthreads();

    unsigned row[16], G[16];
    bool inimg = act && (g0 + r >= 0) && (g0 + r < HH);
    bool interior = act && (r >= HALO) && (r < RB - HALO);
    if (act) {
#pragma unroll
        for (int k = 0; k < 16; ++k) row[k] = Hb[r * TSTRIDE + k];
    }
    bool done = !inimg;     // out-of-image rows stay zero; Hb rows stay 0 too

    for (int it = 0; it < 20; ++it) {
        // phase A: G (horizontal) in regs, H = row|G to smem
        if (!done) {
            unsigned prev = 0u;
#pragma unroll
            for (int k = 0; k < 16; ++k) {
                unsigned m  = row[k];
                unsigned nx = (k < 15) ? row[k + 1] : 0u;
                unsigned g = __funnelshift_l(prev, m, 1) | __funnelshift_r(m, nx, 1);
                G[k] = g;
                Hb[r * TSTRIDE + k] = m | g;
                prev = m;
            }
        }
        __syncthreads();
        // phase B: nv = H(up) | H(dn) | G
        int notsat = 0;
        if (!done) {
            const unsigned* hu = &Hb[(r - 1) * TSTRIDE];
            const unsigned* hd = &Hb[(r + 1) * TSTRIDE];
            bool hasu = (r > 0), hasd = (r < RB - 1);
            unsigned sat = 0xFFFFFFFFu, allw = 0xFFFFFFFFu;
            int ti = (r - HALO) * TSTRIDE;
            int pi = (r - HALO) * WW;
#pragma unroll
            for (int k = 0; k < 16; ++k) {
                unsigned up = hasu ? hu[k] : 0u;
                unsigned dn = hasd ? hd[k] : 0u;
                unsigned nv = up | dn | G[k];
                if (interior) {
                    sat &= nv;
                    if (it == 0) {
                        T[ti + k] = nv;            // first-set=1 for all of m_1
                    } else {
                        unsigned nb = nv & ~row[k];
                        if (nb) {
                            int jv = it + 1;
                            if (jv & 1)  T[ti + k]              |= nb;
                            if (jv & 2)  T[TPLANE + ti + k]     |= nb;
                            if (jv & 4)  T[2 * TPLANE + ti + k] |= nb;
                            if (jv & 8)  T[3 * TPLANE + ti + k] |= nb;
                            if (jv & 16) t4[pi + k]             |= nb;
                        }
                    }
                }
                row[k] = nv;
                allw &= nv;
            }
            if (interior) notsat = (int)(sat != 0xFFFFFFFFu);
            if (allw == 0xFFFFFFFFu) done = true;   // absorbing state; Hb row already all-ones
        }
        int any = __syncthreads_or(notsat);
        if (!any) break;    // all interior rows saturated == fixed point
    }

    // finalize: byte = mf ? (first_set - m0bit) : 20 ; staged coalesced stores
    unsigned* obase = (unsigned*)(g_dist + ((size_t)(b * NC + c) * HH + s * STRIP) * WIDTH);
    for (int grp = 0; grp < 8; ++grp) {
        __syncthreads();
        int lr = r - HALO - grp * 16;
        if (interior && lr >= 0 && lr < 16) {
            int ti = (r - HALO) * TSTRIDE;
            int pi = (r - HALO) * WW;
#pragma unroll
            for (int k = 0; k < 16; ++k) {
                unsigned mf = row[k];
                unsigned m0 = __ldg(mbase + (size_t)(g0 + r) * WW + k);
                unsigned t0 = T[ti + k], t1 = T[TPLANE + ti + k],
                         tt2 = T[2 * TPLANE + ti + k], t3 = T[3 * TPLANE + ti + k],
                         tt4 = t4[pi + k];
#pragma unroll
                for (int u = 0; u < 8; ++u) {
                    unsigned out = 0;
#pragma unroll
                    for (int jj = 0; jj < 4; ++jj) {
                        int j = u * 4 + jj;
                        int jset = (int)((t0 >> j) & 1u) + (int)(((t1 >> j) & 1u) << 1)
                                 + (int)(((tt2 >> j) & 1u) << 2) + (int)(((t3 >> j) & 1u) << 3)
                                 + (int)(((tt4 >> j) & 1u) << 4);
                        int v = ((mf >> j) & 1u) ? (jset - (int)((m0 >> j) & 1u)) : 20;
                        out |= (unsigned)v << (jj * 8);
                    }
                    Hb[lr * 129 + k * 8 + u] = out;
                }
            }
        }
        __syncthreads();
        for (int j = tid; j < 16 * 128; j += TPB)
            obase[grp * 2048 + j] = Hb[(j >> 7) * 129 + (j & 127)];
    }
}

// K2: fused softmax + distance dot; 4 pixels/thread via float4/uchar4
__global__ void k_loss(const float* __restrict__ pred) {
    __shared__ float red[8];
    int g   = blockIdx.x * 256 + threadIdx.x;   // pixel-quad index
    int b   = g >> 16;
    int hw  = (g & 65535) * 4;
    const float4* p  = (const float4*)(pred   + (size_t)b * NC * HW + hw);
    const uchar4* dp = (const uchar4*)(g_dist + (size_t)b * NC * HW + hw);
    float se0 = 0.f, se1 = 0.f, se2 = 0.f, se3 = 0.f;
    float sd0 = 0.f, sd1 = 0.f, sd2 = 0.f, sd3 = 0.f;
#pragma unroll
    for (int c = 0; c < NC; ++c) {
        float4 v = __ldg(p + (size_t)c * (HW / 4));
        uchar4 d = __ldg(dp + (size_t)c * (HW / 4));
        float e0 = fexp(v.x), e1 = fexp(v.y), e2 = fexp(v.z), e3 = fexp(v.w);
        se0 += e0; se1 += e1; se2 += e2; se3 += e3;
        sd0 = fmaf(e0, (float)d.x, sd0);
        sd1 = fmaf(e1, (float)d.y, sd1);
        sd2 = fmaf(e2, (float)d.z, sd2);
        sd3 = fmaf(e3, (float)d.w, sd3);
    }
    float acc = __fdividef(sd0, se0) + __fdividef(sd1, se1)
              + __fdividef(sd2, se2) + __fdividef(sd3, se3);
#pragma unroll
    for (int o = 16; o; o >>= 1) acc += __shfl_down_sync(0xffffffffu, acc, o);
    int tid = threadIdx.x;
    if ((tid & 31) == 0) red[tid >> 5] = acc;
    __syncthreads();
    if (tid < 8) {
        float x = red[tid];
#pragma unroll
        for (int o = 4; o; o >>= 1) x += __shfl_down_sync(0x000000ffu, x, o);
        if (tid == 0) g_part[blockIdx.x] = x;
    }
}

// K3: deterministic final reduction -> mean
__global__ void k_reduce(float* __restrict__ out) {
    __shared__ float red[32];
    int tid = threadIdx.x;
    float v = 0.f;
#pragma unroll
    for (int i = 0; i < NB3 / 1024; ++i) v += g_part[tid + i * 1024];
#pragma unroll
    for (int o = 16; o; o >>= 1) v += __shfl_down_sync(0xffffffffu, v, o);
    if ((tid & 31) == 0) red[tid >> 5] = v;
    __syncthreads();
    if (tid < 32) {
        float x = red[tid];
#pragma unroll
        for (int o = 16; o; o >>= 1) x += __shfl_down_sync(0xffffffffu, x, o);
        if (tid == 0) out[0] = x * (1.0f / ((float)BB * NC * HW));
    }
}

extern "C" void kernel_launch(void* const* d_in, const int* in_sizes, int n_in,
                              void* d_out, int out_size) {
    (void)in_sizes; (void)n_in; (void)out_size;
    const float* pred = (const float*)d_in[0];
    const int*   tgt  = (const int*)d_in[1];

    k_bits<<<8192, 256>>>(tgt);
    k_dilate<<<NBLK, TPB>>>();
    k_loss<<<NB3, 256>>>(pred);
    k_reduce<<<1, 1024>>>((float*)d_out);
}

// round 10
// speedup vs baseline: 1.8888x; 1.8888x over previous
#include <cuda_runtime.h>

#define NC 19
#define BB 8
#define HH 512
#define WIDTH 512
#define HW (HH*WIDTH)
#define WW 16
#define HALO 20
#define STRIP 256
#define RB (STRIP + 2*HALO)   // 296 window rows
#define NSTRIP (HH/STRIP)     // 2
#define NBLK (BB*NC*NSTRIP)   // 304
#define NWORDS (RB*WW)        // 4736 u32
#define NW64 (NWORDS/2)       // 2368 u64 chunks (8 per row)
#define IWORDS (STRIP*WW)     // 4096 interior u32
#define TPB 512
#define NSLOT 5               // ceil(2368/512); slot 4 active for tid<320
#define SMEMSZ ((NWORDS*2 + IWORDS*4)*4)   // M + H + 4 first-set planes = 103424 B
#define NB3 2048              // k_loss blocks (4 px/thread)

// Scratch (static device globals; allocation-free)
__device__ unsigned       g_bits[(size_t)BB*NC*HH*WW];  // ~5 MB packed class masks
__device__ unsigned char  g_dist[(size_t)BB*NC*HW];     // 40 MB distances (0..20)
__device__ unsigned       g_t4[(size_t)NBLK*IWORDS];    // rare 5th first-set plane
__device__ float          g_part[NB3];

// Fast exp on the FMA pipe (|rel err| ~3e-6)
__device__ __forceinline__ float fexp(float x) {
    float y = x * 1.4426950408889634f;
    y = fmaxf(y, -80.0f);
    float z = y + 12582912.0f;
    int   n = __float_as_int(z) - 0x4B400000;
    float f = y - (z - 12582912.0f);
    float p =          1.3333558e-3f;
    p = fmaf(p, f, 9.6181291e-3f);
    p = fmaf(p, f, 5.5504109e-2f);
    p = fmaf(p, f, 2.4022651e-1f);
    p = fmaf(p, f, 6.9314718e-1f);
    p = fmaf(p, f, 1.0f);
    return __int_as_float(__float_as_int(p) + (n << 23));
}

// K0: bit-pack per-class masks via warp ballots (target int32)
__global__ void k_bits(const int* __restrict__ tgt) {
    int g    = blockIdx.x * blockDim.x + threadIdx.x;
    int lane = g & 31;
    int wid  = g >> 5;
    int ww   = wid & 15;
    int h    = (wid >> 4) & 511;
    int b    = wid >> 13;
    int lab  = tgt[(size_t)(b * HH + h) * WIDTH + ww * 32 + lane];
    unsigned my = 0;
#pragma unroll
    for (int c = 0; c < NC; ++c) {
        unsigned bal = __ballot_sync(0xffffffffu, lab == c);
        if (lane == c) my = bal;
    }
    if (lane < NC)
        g_bits[((size_t)(b * NC + lane) * HH + h) * WW + ww] = my;
}

// K1: two-phase bitwise dilation on 64-bit chunks; zero-clamped padding,
// first-set planes, interior saturation exit, exact all-in-image done-freeze.
__global__ void __launch_bounds__(TPB, 2) k_dilate() {
    extern __shared__ unsigned sh[];
    unsigned* M  = sh;                    // NWORDS  current mask
    unsigned* Hb = sh + NWORDS;           // NWORDS  H = m|shl|shr rows
    unsigned* T  = sh + 2 * NWORDS;       // 4*IWORDS first-set planes (bits 0..3)
    uint2* M64 = (uint2*)M;
    uint2* H64 = (uint2*)Hb;

    int blk = blockIdx.x;
    int s   = blk & (NSTRIP - 1);
    int t2  = blk >> 1;
    int c   = t2 % NC;
    int b   = t2 / NC;
    int tid = threadIdx.x;
    int g0  = s * STRIP - HALO;

    const unsigned* mbase = g_bits + (size_t)(b * NC + c) * HH * WW;
    unsigned* t4 = g_t4 + (size_t)blk * IWORDS;
    for (int i = tid; i < NWORDS; i += TPB) {
        int g = g0 + (i >> 4);
        M[i]  = (g >= 0 && g < HH) ? mbase[(size_t)g * WW + (i & 15)] : 0u;
        Hb[i] = 0u;                        // stable 0 for never-written rows
    }
    for (int i = tid; i < 4 * IWORDS; i += TPB) T[i] = 0u;
    for (int i = tid; i < IWORDS; i += TPB) t4[i] = 0u;
    __syncthreads();

    uint2 mreg[NSLOT], G[NSLOT];
    bool inimg[NSLOT], act[NSLOT], interior[NSLOT];
    bool allout = true;
#pragma unroll
    for (int j = 0; j < NSLOT; ++j) {
        int idx = j * TPB + tid;           // u64-chunk index
        act[j] = (idx < NW64);
        mreg[j] = act[j] ? M64[idx] : make_uint2(0u, 0u);
        int r = idx >> 3;
        int g = g0 + r;
        inimg[j]    = act[j] && (g >= 0) && (g < HH);
        interior[j] = act[j] && (r >= HALO) && (r < RB - HALO);
        allout &= !inimg[j];
    }
    bool done = allout;
    bool fixpend = false;

    for (int it = 0; it < 20; ++it) {
        // phase A: H = m | shl(m) | shr(m)  (64-bit, carries via 32-bit edge reads)
        if (!done) {
#pragma unroll
            for (int j = 0; j < NSLOT; ++j) {
                if (!act[j]) continue;
                int idx = j * TPB + tid;
                int k = idx & 7;
                uint2 m = mreg[j];
                unsigned lwh = (k > 0) ? M[2 * idx - 1] : 0u;
                unsigned rwl = (k < 7) ? M[2 * idx + 2] : 0u;
                uint2 g;
                g.x = __funnelshift_l(lwh, m.x, 1) | __funnelshift_r(m.x, m.y, 1);
                g.y = __funnelshift_l(m.x, m.y, 1) | __funnelshift_r(m.y, rwl, 1);
                G[j] = g;
                H64[idx] = make_uint2(m.x | g.x, m.y | g.y);
            }
        } else if (fixpend) {
            // all in-image words saturated (absorbing): H == m exactly
#pragma unroll
            for (int j = 0; j < NSLOT; ++j)
                if (inimg[j]) H64[j * TPB + tid] = mreg[j];
            fixpend = false;
        }
        __syncthreads();
        // phase B: nv = (H(up) | H(dn) | G) clamped outside the image
        int notsat = 0;
        if (!done) {
            unsigned satin = 0xFFFFFFFFu;   // over interior words (block exit)
            unsigned satim = 0xFFFFFFFFu;   // over all in-image words (freeze)
#pragma unroll
            for (int j = 0; j < NSLOT; ++j) {
                if (!act[j]) continue;
                int idx = j * TPB + tid;
                int r = idx >> 3;
                uint2 up = (r > 0)      ? H64[idx - 8] : make_uint2(0u, 0u);
                uint2 dn = (r < RB - 1) ? H64[idx + 8] : make_uint2(0u, 0u);
                uint2 m = mreg[j];
                uint2 nv;
                nv.x = inimg[j] ? (up.x | dn.x | G[j].x) : 0u;
                nv.y = inimg[j] ? (up.y | dn.y | G[j].y) : 0u;
                if (inimg[j]) satim &= nv.x & nv.y;
                if (interior[j]) {
                    satin &= nv.x & nv.y;
                    int pi = idx - HALO * 8;          // u64 plane index
                    if (it == 0) {
                        ((uint2*)T)[pi] = nv;         // first-set=1 for all of m_1
                    } else {
                        unsigned nbx = nv.x & ~m.x, nby = nv.y & ~m.y;
                        if (nbx | nby) {
                            int jv = it + 1;
                            if (jv & 1) { uint2* tp = (uint2*)T + pi;
                                uint2 t = *tp; tp->x = t.x | nbx; tp->y = t.y | nby; }
                            if (jv & 2) { uint2* tp = (uint2*)(T + IWORDS) + pi;
                                uint2 t = *tp; tp->x = t.x | nbx; tp->y = t.y | nby; }
                            if (jv & 4) { uint2* tp = (uint2*)(T + 2 * IWORDS) + pi;
                                uint2 t = *tp; tp->x = t.x | nbx; tp->y = t.y | nby; }
                            if (jv & 8) { uint2* tp = (uint2*)(T + 3 * IWORDS) + pi;
                                uint2 t = *tp; tp->x = t.x | nbx; tp->y = t.y | nby; }
                            if (jv & 16) {
                                if (nbx) t4[2 * pi]     |= nbx;
                                if (nby) t4[2 * pi + 1] |= nby;
                            }
                        }
                    }
                }
                mreg[j] = nv;
                M64[idx] = nv;
            }
            notsat = (int)(satin != 0xFFFFFFFFu);
            if (satim == 0xFFFFFFFFu) { done = true; fixpend = true; }
        }
        int any = __syncthreads_or(notsat);
        if (!any) break;   // all interior words saturated == fixed point
    }

    // finalize: byte = mf ? (first_set - m0bit) : 20 ; coalesced u32 stores
    unsigned* obase = (unsigned*)(g_dist + ((size_t)(b * NC + c) * HH + s * STRIP) * WIDTH);
    const unsigned* m0base = mbase + (size_t)(s * STRIP) * WW;
    for (int q = tid; q < STRIP * WIDTH / 4; q += TPB) {
        int r  = q >> 7;
        int u  = q & 127;
        int w  = u >> 3;
        int jb = (u & 7) * 4;
        int pi = r * WW + w;
        unsigned mf = M[(r + HALO) * WW + w];
        unsigned m0 = __ldg(m0base + r * WW + w);
        unsigned t0 = T[pi], t1 = T[IWORDS + pi], t2p = T[2 * IWORDS + pi],
                 t3 = T[3 * IWORDS + pi], tt4 = t4[pi];
        unsigned out = 0;
#pragma unroll
        for (int jj = 0; jj < 4; ++jj) {
            int j = jb + jj;
            int jset = (int)((t0 >> j) & 1u) + (int)(((t1 >> j) & 1u) << 1)
                     + (int)(((t2p >> j) & 1u) << 2) + (int)(((t3 >> j) & 1u) << 3)
                     + (int)(((tt4 >> j) & 1u) << 4);
            int v = ((mf >> j) & 1u) ? (jset - (int)((m0 >> j) & 1u)) : 20;
            out |= (unsigned)v << (jj * 8);
        }
        obase[q] = out;
    }
}

// K2: fused softmax + distance dot; 4 pixels/thread via float4/uchar4
__global__ void k_loss(const float* __restrict__ pred) {
    __shared__ float red[8];
    int g   = blockIdx.x * 256 + threadIdx.x;   // pixel-quad index
    int b   = g >> 16;
    int hw  = (g & 65535) * 4;
    const float4* p  = (const float4*)(pred   + (size_t)b * NC * HW + hw);
    const uchar4* dp = (const uchar4*)(g_dist + (size_t)b * NC * HW + hw);
    float se0 = 0.f, se1 = 0.f, se2 = 0.f, se3 = 0.f;
    float sd0 = 0.f, sd1 = 0.f, sd2 = 0.f, sd3 = 0.f;
#pragma unroll
    for (int c = 0; c < NC; ++c) {
        float4 v = __ldg(p + (size_t)c * (HW / 4));
        uchar4 d = __ldg(dp + (size_t)c * (HW / 4));
        float e0 = fexp(v.x), e1 = fexp(v.y), e2 = fexp(v.z), e3 = fexp(v.w);
        se0 += e0; se1 += e1; se2 += e2; se3 += e3;
        sd0 = fmaf(e0, (float)d.x, sd0);
        sd1 = fmaf(e1, (float)d.y, sd1);
        sd2 = fmaf(e2, (float)d.z, sd2);
        sd3 = fmaf(e3, (float)d.w, sd3);
    }
    float acc = __fdividef(sd0, se0) + __fdividef(sd1, se1)
              + __fdividef(sd2, se2) + __fdividef(sd3, se3);
#pragma unroll
    for (int o = 16; o; o >>= 1) acc += __shfl_down_sync(0xffffffffu, acc, o);
    int tid = threadIdx.x;
    if ((tid & 31) == 0) red[tid >> 5] = acc;
    __syncthreads();
    if (tid < 8) {
        float x = red[tid];
#pragma unroll
        for (int o = 4; o; o >>= 1) x += __shfl_down_sync(0x000000ffu, x, o);
        if (tid == 0) g_part[blockIdx.x] = x;
    }
}

// K3: deterministic final reduction -> mean
__global__ void k_reduce(float* __restrict__ out) {
    __shared__ float red[32];
    int tid = threadIdx.x;
    float v = 0.f;
#pragma unroll
    for (int i = 0; i < NB3 / 1024; ++i) v += g_part[tid + i * 1024];
#pragma unroll
    for (int o = 16; o; o >>= 1) v += __shfl_down_sync(0xffffffffu, v, o);
    if ((tid & 31) == 0) red[tid >> 5] = v;
    __syncthreads();
    if (tid < 32) {
        float x = red[tid];
#pragma unroll
        for (int o = 16; o; o >>= 1) x += __shfl_down_sync(0xffffffffu, x, o);
        if (tid == 0) out[0] = x * (1.0f / ((float)BB * NC * HW));
    }
}

extern "C" void kernel_launch(void* const* d_in, const int* in_sizes, int n_in,
                              void* d_out, int out_size) {
    (void)in_sizes; (void)n_in; (void)out_size;
    const float* pred = (const float*)d_in[0];
    const int*   tgt  = (const int*)d_in[1];

    cudaFuncSetAttribute(k_dilate, cudaFuncAttributeMaxDynamicSharedMemorySize, SMEMSZ);

    k_bits<<<8192, 256>>>(tgt);
    k_dilate<<<NBLK, TPB, SMEMSZ>>>();
    k_loss<<<NB3, 256>>>(pred);
    k_reduce<<<1, 1024>>>((float*)d_out);
}